// round 12
// baseline (speedup 1.0000x reference)
#include <cuda_runtime.h>
#include <cuda_bf16.h>

// ---------------------------------------------------------------------------
// MambaAudioClassifier: patchify-conv -> 6x(LN -> GRU -> residual) -> LN ->
// mean pool -> 2-layer head.  B=32, S=1000, D=256, 3D=768, PATCH=160.
// fp32.  Recurrence: 4-CTA clusters, weights in registers, f32x2 FFMA dot,
// h-exchange via 256B cp.async.bulk (smem->peer smem) + mbarrier tx,
// MUFU tanh gates.  proj GEMM: f32x2 packed FFMA, 128x64 tile.
// ---------------------------------------------------------------------------

#define BATCH   32
#define SEQ     1000
#define DM      256
#define G3      768
#define PATCH   160
#define NLAYERS 6
#define MROWS   (BATCH * SEQ)       // 32000

// Scratch (device globals: no allocation allowed)
__device__ float g_x [MROWS * DM];   // residual stream
__device__ float g_xn[MROWS * DM];   // layernorm output
__device__ float g_xp[MROWS * G3];   // input projections
__device__ float g_emb[BATCH * DM];

__device__ __forceinline__ float gelu_f(float x) {
    return 0.5f * x * (1.0f + erff(x * 0.70710678118654752f));
}
// HW tanh (MUFU.TANH), ~1e-5 error — far inside the 1e-3 budget.
__device__ __forceinline__ float tanh_hw(float x) {
    float y;
    asm("tanh.approx.f32 %0, %1;" : "=f"(y) : "f"(x));
    return y;
}
__device__ __forceinline__ float sigmoid_hw(float x) {
    return fmaf(0.5f, tanh_hw(0.5f * x), 0.5f);
}

// Blackwell packed fp32 ops on (lo,hi) float pairs.
__device__ __forceinline__ void ffma2(unsigned long long& d,
                                      unsigned long long a,
                                      unsigned long long b) {
    asm("fma.rn.f32x2 %0, %1, %2, %0;" : "+l"(d) : "l"(a), "l"(b));
}
__device__ __forceinline__ unsigned long long fadd2(unsigned long long a,
                                                    unsigned long long b) {
    unsigned long long r;
    asm("add.rn.f32x2 %0, %1, %2;" : "=l"(r) : "l"(a), "l"(b));
    return r;
}
__device__ __forceinline__ unsigned long long fdup2(float v) {
    unsigned long long r;
    asm("mov.b64 %0, {%1, %1};" : "=l"(r) : "r"(__float_as_uint(v)));
    return r;
}

__device__ __forceinline__ unsigned smem_u32(const void* p) {
    return (unsigned)__cvta_generic_to_shared(p);
}

// mbarrier wait (parity, acquire) — sleep-based try_wait loop.
__device__ __forceinline__ void mbar_wait_parity(unsigned mb, unsigned par) {
    unsigned done;
    asm volatile(
        "{\n\t.reg .pred p;\n\t"
        "mbarrier.try_wait.parity.acquire.cta.shared::cta.b64 p, [%1], %2;\n\t"
        "selp.b32 %0, 1, 0, p;\n\t}"
        : "=r"(done) : "r"(mb), "r"(par) : "memory");
    if (!done) {
        asm volatile(
            "{\n\t.reg .pred P1;\n\t"
            "WAIT_LOOP_%=:\n\t"
            "mbarrier.try_wait.parity.acquire.cta.shared::cta.b64 P1, [%0], %1, 0x989680;\n\t"
            "@P1 bra.uni WAIT_DONE_%=;\n\t"
            "bra.uni WAIT_LOOP_%=;\n\t"
            "WAIT_DONE_%=:\n\t}"
            :: "r"(mb), "r"(par) : "memory");
    }
}

// ---------------------------------------------------------------------------
// Conv front-end as a GEMM: A = waveform reshaped [32000,160] (contiguous),
// W = conv_w [K=160, N=256] (K-major).  Epilogue: exact GELU + pos_emb.
// ---------------------------------------------------------------------------
__global__ __launch_bounds__(256) void conv_gemm_kernel(
    const float* __restrict__ wave, const float* __restrict__ cw,
    const float* __restrict__ pos)
{
    __shared__ float As[16][64 + 4];
    __shared__ float Ws[16][64 + 4];
    const int bx = blockIdx.x;          // n tile: 0..3
    const int by = blockIdx.y;          // m tile: 0..499
    const int tid = threadIdx.x;

    const float* Ab = wave + by * 64 * PATCH;
    const int lr = tid >> 2;            // 0..63
    const int lc = (tid & 3) << 2;      // 0,4,8,12
    const int wk = tid >> 4;            // 0..15
    const int wn = (tid & 15) << 2;     // 0..60

    const int tr = (tid >> 4) << 2;     // out row base
    const int tc = (tid & 15) << 2;     // out col base

    float acc[4][4] = {};
    for (int bk = 0; bk < PATCH; bk += 16) {
        float4 a = *(const float4*)(Ab + lr * PATCH + bk + lc);
        As[lc + 0][lr] = a.x; As[lc + 1][lr] = a.y;
        As[lc + 2][lr] = a.z; As[lc + 3][lr] = a.w;
        float4 w = *(const float4*)(cw + (bk + wk) * DM + bx * 64 + wn);
        Ws[wk][wn + 0] = w.x; Ws[wk][wn + 1] = w.y;
        Ws[wk][wn + 2] = w.z; Ws[wk][wn + 3] = w.w;
        __syncthreads();
#pragma unroll
        for (int k = 0; k < 16; k++) {
            float am[4], wv[4];
#pragma unroll
            for (int i = 0; i < 4; i++) am[i] = As[k][tr + i];
#pragma unroll
            for (int j = 0; j < 4; j++) wv[j] = Ws[k][tc + j];
#pragma unroll
            for (int i = 0; i < 4; i++)
#pragma unroll
                for (int j = 0; j < 4; j++) acc[i][j] += am[i] * wv[j];
        }
        __syncthreads();
    }
#pragma unroll
    for (int i = 0; i < 4; i++) {
        const int m = by * 64 + tr + i;
        const int s = m % SEQ;
#pragma unroll
        for (int j = 0; j < 4; j++) {
            const int col = bx * 64 + tc + j;
            g_x[m * DM + col] = gelu_f(acc[i][j]) + pos[s * DM + col];
        }
    }
}

// ---------------------------------------------------------------------------
// LayerNorm over last dim (256).  One block per row.  Reads g_x, writes g_xn.
// ---------------------------------------------------------------------------
__global__ __launch_bounds__(256) void ln_kernel(
    const float* __restrict__ sc, const float* __restrict__ bi)
{
    const int m = blockIdx.x;
    const int t = threadIdx.x;
    float v = g_x[m * DM + t];
    float s = v, s2 = v * v;
#pragma unroll
    for (int o = 16; o > 0; o >>= 1) {
        s  += __shfl_xor_sync(0xffffffffu, s,  o);
        s2 += __shfl_xor_sync(0xffffffffu, s2, o);
    }
    __shared__ float ws[8], ws2[8];
    __shared__ float mu_s, rs_s;
    if ((t & 31) == 0) { ws[t >> 5] = s; ws2[t >> 5] = s2; }
    __syncthreads();
    if (t == 0) {
        float a = 0.f, a2 = 0.f;
#pragma unroll
        for (int i = 0; i < 8; i++) { a += ws[i]; a2 += ws2[i]; }
        float mu = a * (1.0f / DM);
        float var = a2 * (1.0f / DM) - mu * mu;
        mu_s = mu;
        rs_s = rsqrtf(var + 1e-5f);
    }
    __syncthreads();
    g_xn[m * DM + t] = (v - mu_s) * rs_s * sc[t] + bi[t];
}

// ---------------------------------------------------------------------------
// Input projection GEMM: g_xp = g_xn @ W^T + b.  W is [768,256] K-major.
// M=32000, N=768, K=256.  CTA tile 128x64, per-thread 8x4 with f32x2 packed
// FFMA (rows packed in pairs; B scalars duplicated into both lanes).
// ---------------------------------------------------------------------------
__global__ __launch_bounds__(256) void proj_gemm_kernel(
    const float* __restrict__ W, const float* __restrict__ bias)
{
    __shared__ float As[16][132];   // [k][m], 128 rows (+pad, keeps 16B align)
    __shared__ float Ws[16][68];    // [k][n], 64 cols
    const int bx = blockIdx.x;      // 0..11 (N tiles)
    const int by = blockIdx.y;      // 0..249 (M tiles)
    const int tid = threadIdx.x;

    const float* Ab = g_xn + (size_t)by * 128 * DM;
    const float* Wb = W + (size_t)bx * 64 * DM;

    const int lr = tid >> 1;            // 0..127 (A row)
    const int lk = (tid & 1) << 3;      // 0 or 8 (A k-offset)
    const int wr = tid >> 2;            // 0..63  (B row)
    const int wk = (tid & 3) << 2;      // 0,4,8,12 (B k-offset)
    const int tr = (tid >> 4) << 3;     // out row base (0..120, step 8)
    const int tc = (tid & 15) << 2;     // out col base (0..60)

    unsigned long long acc[4][4];
#pragma unroll
    for (int i = 0; i < 4; i++)
#pragma unroll
        for (int j = 0; j < 4; j++) acc[i][j] = 0ull;

    for (int bk = 0; bk < DM; bk += 16) {
        float4 a0 = *(const float4*)(Ab + lr * DM + bk + lk);
        float4 a1 = *(const float4*)(Ab + lr * DM + bk + lk + 4);
        As[lk + 0][lr] = a0.x; As[lk + 1][lr] = a0.y;
        As[lk + 2][lr] = a0.z; As[lk + 3][lr] = a0.w;
        As[lk + 4][lr] = a1.x; As[lk + 5][lr] = a1.y;
        As[lk + 6][lr] = a1.z; As[lk + 7][lr] = a1.w;
        float4 w = *(const float4*)(Wb + wr * DM + bk + wk);
        Ws[wk + 0][wr] = w.x; Ws[wk + 1][wr] = w.y;
        Ws[wk + 2][wr] = w.z; Ws[wk + 3][wr] = w.w;
        __syncthreads();
#pragma unroll
        for (int k = 0; k < 16; k++) {
            ulonglong2 av0 = *(const ulonglong2*)&As[k][tr];      // rows tr..tr+3
            ulonglong2 av1 = *(const ulonglong2*)&As[k][tr + 4];  // rows tr+4..tr+7
            float4 wv = *(const float4*)&Ws[k][tc];
            unsigned long long w0 = fdup2(wv.x), w1 = fdup2(wv.y);
            unsigned long long w2 = fdup2(wv.z), w3 = fdup2(wv.w);
            ffma2(acc[0][0], av0.x, w0); ffma2(acc[0][1], av0.x, w1);
            ffma2(acc[0][2], av0.x, w2); ffma2(acc[0][3], av0.x, w3);
            ffma2(acc[1][0], av0.y, w0); ffma2(acc[1][1], av0.y, w1);
            ffma2(acc[1][2], av0.y, w2); ffma2(acc[1][3], av0.y, w3);
            ffma2(acc[2][0], av1.x, w0); ffma2(acc[2][1], av1.x, w1);
            ffma2(acc[2][2], av1.x, w2); ffma2(acc[2][3], av1.x, w3);
            ffma2(acc[3][0], av1.y, w0); ffma2(acc[3][1], av1.y, w1);
            ffma2(acc[3][2], av1.y, w2); ffma2(acc[3][3], av1.y, w3);
        }
        __syncthreads();
    }

    const int gcol = bx * 64 + tc;
    float bj0 = bias[gcol + 0], bj1 = bias[gcol + 1];
    float bj2 = bias[gcol + 2], bj3 = bias[gcol + 3];
#pragma unroll
    for (int i2 = 0; i2 < 4; i2++) {
        const int r0 = by * 128 + tr + 2 * i2;
        float* C0 = g_xp + (size_t)r0 * G3 + gcol;
        float* C1 = C0 + G3;
        union { unsigned long long u; float2 f; } c0, c1, c2, c3;
        c0.u = acc[i2][0]; c1.u = acc[i2][1];
        c2.u = acc[i2][2]; c3.u = acc[i2][3];
        C0[0] = c0.f.x + bj0; C0[1] = c1.f.x + bj1;
        C0[2] = c2.f.x + bj2; C0[3] = c3.f.x + bj3;
        C1[0] = c0.f.y + bj0; C1[1] = c1.f.y + bj1;
        C1[2] = c2.f.y + bj2; C1[3] = c3.f.y + bj3;
    }
}

// ---------------------------------------------------------------------------
// GRU recurrence.  One 4-CTA cluster per batch; each CTA owns a 64-dim slice
// (192 gate rows).  384 threads: (row 0..191, K-half 0..1); 128 f32 weights
// per thread in registers, 4-accumulator f32x2 dot.
// Gates: warp 0 only, 2 dims/thread (float2), MUFU tanh.
// h exchange: gates write h_new into a double-buffered 256B staging slice;
// one thread issues FOUR cp.async.bulk (smem -> each CTA's h_buf slot, incl.
// self), tx-counted on each target's parity mbarrier (expect_tx 1024B).
// Wait = try_wait.parity.acquire.  No barrier.cluster in the loop.
// Race-safety: a peer cannot advance past step t until our step-t copy fully
// landed (tx gating), so stage[2] double-buffering suffices and h_buf[cur]
// readers are protected by the full-CTA __syncthreads before sending.
// ---------------------------------------------------------------------------
__global__ __launch_bounds__(384, 1) __cluster_dims__(4, 1, 1)
void recur_kernel(const float* __restrict__ Whh,
                  const float* __restrict__ bhh)
{
    __shared__ __align__(16) float h_buf[2][DM];
    __shared__ __align__(16) float h_stage[2][64];
    __shared__ __align__(8)  float gh_sh[192];
    __shared__ __align__(8)  unsigned long long mbar[2];
    __shared__ unsigned tbl_dst[2][4];   // [parity][peer] remote h_buf slot
    __shared__ unsigned tbl_mb [2][4];   // [parity][peer] remote mbar

    const int tid   = threadIdx.x;
    const int b     = blockIdx.x >> 2;
    const int slice = blockIdx.x & 3;
    const int d0    = slice * 64;
    const int row   = tid >> 1;         // 0..191
    const int half  = tid & 1;
    const int gate  = row >> 6;         // 0,1,2
    const int dloc  = row & 63;
    const int grow  = gate * DM + d0 + dloc;

    // preload this thread's 128 weights as 64 packed f32x2 pairs
    unsigned long long w2[64];
    {
        const ulonglong2* wp =
            (const ulonglong2*)(Whh + grow * DM + half * 128);
#pragma unroll
        for (int i = 0; i < 32; i++) {
            ulonglong2 v = wp[i];
            w2[2 * i]     = v.x;
            w2[2 * i + 1] = v.y;
        }
    }
    if (tid < DM) { h_buf[0][tid] = 0.0f; h_buf[1][tid] = 0.0f; }

    if (tid == 0) {
        asm volatile("mbarrier.init.shared.b64 [%0], %1;"
                     :: "r"(smem_u32(&mbar[0])), "r"(1u) : "memory");
        asm volatile("mbarrier.init.shared.b64 [%0], %1;"
                     :: "r"(smem_u32(&mbar[1])), "r"(1u) : "memory");
    }
    if (tid < 8) {
        const int p = tid >> 2, peer = tid & 3;
        unsigned ldst = smem_u32(&h_buf[p ^ 1][d0]);
        unsigned lmb  = smem_u32(&mbar[p]);
        unsigned rdst, rmb;
        asm("mapa.shared::cluster.u32 %0, %1, %2;"
            : "=r"(rdst) : "r"(ldst), "r"(peer));
        asm("mapa.shared::cluster.u32 %0, %1, %2;"
            : "=r"(rmb) : "r"(lmb), "r"(peer));
        tbl_dst[p][peer] = rdst;
        tbl_mb [p][peer] = rmb;
    }
    __syncthreads();

    // cluster-wide init barrier: peers' mbarriers + zeroed h visible before
    // any bulk copy targets them.
    asm volatile("barrier.cluster.arrive.aligned;" ::: "memory");
    asm volatile("barrier.cluster.wait.aligned;"   ::: "memory");

    const float* xpb = g_xp + (size_t)(b * SEQ) * G3;
    int cur = 0;

    // gate-warp per-thread biases (2 dims each) and step-0 x prefetch
    float2 xr2 = {0.f, 0.f}, xz2 = xr2, xn2 = xr2, xo2 = xr2, bhn2 = xr2;
    if (tid < 32) {
        const int d = d0 + 2 * tid;
        float2 bhr2 = *(const float2*)&bhh[d];
        float2 bhz2 = *(const float2*)&bhh[DM + d];
        bhn2        = *(const float2*)&bhh[2 * DM + d];
        xr2 = *(const float2*)&xpb[d];
        xz2 = *(const float2*)&xpb[DM + d];
        xn2 = *(const float2*)&xpb[2 * DM + d];
        xo2 = *(const float2*)&g_x[(size_t)(b * SEQ) * DM + d];
        xr2.x += bhr2.x; xr2.y += bhr2.y;
        xz2.x += bhz2.x; xz2.y += bhz2.y;
        // biases for later steps folded at each prefetch below
        // stash bhr/bhz in registers by re-deriving: keep them
        // (compiler keeps bhr2/bhz2 live via the loop below)
        // -- handled by reloading them here each step is avoided by
        //    keeping them in dedicated registers:
        xr2.x = xr2.x; // no-op
        // store persistent copies
        // (use gh_sh scratch is not safe; keep in regs)
        // bhr2/bhz2 live-range extended via asm-free usage in loop
        ((float2*)&h_stage[0][0])[tid & 0] = ((float2*)&h_stage[0][0])[tid & 0]; // no-op
        // fall through
        // NOTE: bhr2/bhz2 re-folded in the prefetch at loop bottom.
        // To keep them live, store into stage-free registers:
        xo2 = xo2; // no-op
        // persistent bias registers:
        // (declared below)
        h_stage[0][2 * tid]     = 0.f;  // init staging (benign)
        h_stage[0][2 * tid + 1] = 0.f;
        h_stage[1][2 * tid]     = 0.f;
        h_stage[1][2 * tid + 1] = 0.f;
        // re-save biases
        gh_sh[0] = gh_sh[0]; // no-op
        // keep bhr2/bhz2:
        bhn2 = bhn2;
        // store to locals:
        // (see bhr_x.. below)
        xr2 = xr2;
        // carried registers:
        // bhr_x etc.
        // (assigned now)
        // ---
        // real persistent copies:
        // (must be outside if-block scope; see below)
        ;
    }
    // persistent bias regs for the gate warp (folded each prefetch)
    float bhr_x = 0.f, bhr_y = 0.f, bhz_x = 0.f, bhz_y = 0.f;
    if (tid < 32) {
        const int d = d0 + 2 * tid;
        float2 t0 = *(const float2*)&bhh[d];
        float2 t1 = *(const float2*)&bhh[DM + d];
        bhr_x = t0.x; bhr_y = t0.y; bhz_x = t1.x; bhz_y = t1.y;
    }

    for (int step = 0; step < SEQ; step++) {
        const int p = step & 1;
        const unsigned mb_local = smem_u32(&mbar[p]);
        if (tid == 0) {
            asm volatile("mbarrier.arrive.expect_tx.shared.b64 _, [%0], %1;"
                         :: "r"(mb_local), "r"(1024u) : "memory");
        }

        // partial dot: 64 packed FMAs per thread over 4 independent accs
        unsigned long long a0 = 0ull, a1 = 0ull, a2 = 0ull, a3 = 0ull;
        const ulonglong2* hp = (const ulonglong2*)(&h_buf[cur][half * 128]);
#pragma unroll
        for (int i = 0; i < 16; i++) {
            ulonglong2 hv0 = hp[2 * i];
            ulonglong2 hv1 = hp[2 * i + 1];
            ffma2(a0, w2[4 * i + 0], hv0.x);
            ffma2(a1, w2[4 * i + 1], hv0.y);
            ffma2(a2, w2[4 * i + 2], hv1.x);
            ffma2(a3, w2[4 * i + 3], hv1.y);
        }
        unsigned long long accp = fadd2(fadd2(a0, a1), fadd2(a2, a3));
        union { unsigned long long u; float2 f; } cv; cv.u = accp;
        float sum = cv.f.x + cv.f.y;
        sum += __shfl_down_sync(0xffffffffu, sum, 1);
        if (half == 0) gh_sh[row] = sum;
        __syncthreads();

        if (tid < 32) {
            const int d  = d0 + 2 * tid;
            float2 ghr = *(const float2*)&gh_sh[2 * tid];
            float2 ghz = *(const float2*)&gh_sh[64 + 2 * tid];
            float2 ghn = *(const float2*)&gh_sh[128 + 2 * tid];
            float rx = sigmoid_hw(xr2.x + ghr.x);
            float ry = sigmoid_hw(xr2.y + ghr.y);
            float zx = sigmoid_hw(xz2.x + ghz.x);
            float zy = sigmoid_hw(xz2.y + ghz.y);
            float nx = tanh_hw(xn2.x + rx * (ghn.x + bhn2.x));
            float ny = tanh_hw(xn2.y + ry * (ghn.y + bhn2.y));
            float2 hp2 = *(const float2*)&h_buf[cur][d];
            float2 hn2;
            hn2.x = nx + zx * (hp2.x - nx);
            hn2.y = ny + zy * (hp2.y - ny);
            float2 res;
            res.x = xo2.x + hn2.x;
            res.y = xo2.y + hn2.y;
            *(float2*)&g_x[(size_t)(b * SEQ + step) * DM + d] = res;
            *(float2*)&h_stage[p][2 * tid] = hn2;
            __syncwarp();
            if (tid == 0) {
                asm volatile("fence.proxy.async.shared::cta;" ::: "memory");
                unsigned src = smem_u32(&h_stage[p][0]);
#pragma unroll
                for (int peer = 0; peer < 4; peer++) {
                    asm volatile(
                        "cp.async.bulk.shared::cluster.shared::cta"
                        ".mbarrier::complete_tx::bytes [%0], [%1], %2, [%3];"
                        :: "r"(tbl_dst[p][peer]), "r"(src), "r"(256u),
                           "r"(tbl_mb[p][peer]) : "memory");
                }
            }
            // prefetch next step's inputs while copies are in flight
            if (step + 1 < SEQ) {
                const float* px = xpb + (size_t)(step + 1) * G3;
                xr2 = *(const float2*)&px[d];
                xz2 = *(const float2*)&px[DM + d];
                xn2 = *(const float2*)&px[2 * DM + d];
                xo2 = *(const float2*)&g_x[(size_t)(b * SEQ + step + 1) * DM + d];
                xr2.x += bhr_x; xr2.y += bhr_y;
                xz2.x += bhz_x; xz2.y += bhz_y;
            }
        }

        // wait for all 1024 bytes (4 slices) + our arrival for this parity
        mbar_wait_parity(mb_local, (unsigned)((step >> 1) & 1));
        cur ^= 1;
    }

    // no CTA may exit while peers might still target its SMEM
    asm volatile("barrier.cluster.arrive.aligned;" ::: "memory");
    asm volatile("barrier.cluster.wait.aligned;"   ::: "memory");
}

// ---------------------------------------------------------------------------
// Mean over sequence: emb[b,d] = mean_t g_xn[b,t,d]
// ---------------------------------------------------------------------------
__global__ __launch_bounds__(256) void mean_kernel()
{
    const int b = blockIdx.x;
    const int t = threadIdx.x;
    float a = 0.f;
#pragma unroll 8
    for (int s = 0; s < SEQ; s++) a += g_xn[(b * SEQ + s) * DM + t];
    g_emb[b * DM + t] = a * (1.0f / SEQ);
}

// ---------------------------------------------------------------------------
// Head: gelu(emb @ w1 + b1) @ w2 + b2.  One block per batch, 128 threads.
// ---------------------------------------------------------------------------
__global__ __launch_bounds__(128) void head_kernel(
    const float* __restrict__ w1, const float* __restrict__ b1,
    const float* __restrict__ w2, const float* __restrict__ b2,
    float* __restrict__ out)
{
    const int b = blockIdx.x;
    const int t = threadIdx.x;
    __shared__ float e_sh[DM];
    __shared__ float h_sh[128];
    e_sh[t]       = g_emb[b * DM + t];
    e_sh[t + 128] = g_emb[b * DM + t + 128];
    __syncthreads();
    float a = b1[t];
#pragma unroll 8
    for (int d = 0; d < DM; d++) a += e_sh[d] * w1[d * 128 + t];
    h_sh[t] = gelu_f(a);
    __syncthreads();
    if (t < 8) {
        float o = b2[t];
#pragma unroll 8
        for (int i = 0; i < 128; i++) o += h_sh[i] * w2[i * 8 + t];
        out[b * 8 + t] = o;
    }
}

// ---------------------------------------------------------------------------
extern "C" void kernel_launch(void* const* d_in, const int* in_sizes, int n_in,
                              void* d_out, int out_size)
{
    const float* waveform    = (const float*)d_in[0];   // [32,160000]
    const float* conv_w      = (const float*)d_in[1];   // [160,256]
    const float* pos_emb     = (const float*)d_in[2];   // [6000,256]
    const float* ln_scale    = (const float*)d_in[3];   // [6,256]
    const float* ln_bias     = (const float*)d_in[4];   // [6,256]
    const float* w_ih        = (const float*)d_in[5];   // [6,768,256]
    const float* w_hh        = (const float*)d_in[6];   // [6,768,256]
    const float* b_ih        = (const float*)d_in[7];   // [6,768]
    const float* b_hh        = (const float*)d_in[8];   // [6,768]
    const float* fnorm_scale = (const float*)d_in[9];   // [256]
    const float* fnorm_bias  = (const float*)d_in[10];  // [256]
    const float* head_w1     = (const float*)d_in[11];  // [256,128]
    const float* head_b1     = (const float*)d_in[12];  // [128]
    const float* head_w2     = (const float*)d_in[13];  // [128,8]
    const float* head_b2     = (const float*)d_in[14];  // [8]
    float* out = (float*)d_out;

    // front-end conv + gelu + pos -> g_x
    conv_gemm_kernel<<<dim3(DM / 64, MROWS / 64), 256>>>(waveform, conv_w, pos_emb);

    for (int l = 0; l < NLAYERS; l++) {
        ln_kernel<<<MROWS, 256>>>(ln_scale + l * DM, ln_bias + l * DM);
        proj_gemm_kernel<<<dim3(G3 / 64, MROWS / 128), 256>>>(
            w_ih + (size_t)l * G3 * DM, b_ih + l * G3);
        recur_kernel<<<BATCH * 4, 384>>>(
            w_hh + (size_t)l * G3 * DM, b_hh + l * G3);
    }

    // final layernorm -> g_xn, mean pool, head
    ln_kernel<<<MROWS, 256>>>(fnorm_scale, fnorm_bias);
    mean_kernel<<<BATCH, 256>>>();
    head_kernel<<<BATCH, 128>>>(head_w1, head_b1, head_w2, head_b2, out);
}

// round 13
// speedup vs baseline: 1.1472x; 1.1472x over previous
#include <cuda_runtime.h>
#include <cuda_bf16.h>

// ---------------------------------------------------------------------------
// MambaAudioClassifier: patchify-conv -> 6x(LN -> GRU -> residual) -> LN ->
// mean pool -> 2-layer head.  B=32, S=1000, D=256, 3D=768, PATCH=160.
// fp32.  Recurrence: 4-CTA clusters, weights in registers, f32x2 FFMA dot,
// h-exchange via paired st.async.b64 + mbarrier tx, MUFU tanh gates.
// proj GEMM: f32x2 packed FFMA, 128x64 tile.
// ---------------------------------------------------------------------------

#define BATCH   32
#define SEQ     1000
#define DM      256
#define G3      768
#define PATCH   160
#define NLAYERS 6
#define MROWS   (BATCH * SEQ)       // 32000

// Scratch (device globals: no allocation allowed)
__device__ float g_x [MROWS * DM];   // residual stream
__device__ float g_xn[MROWS * DM];   // layernorm output
__device__ float g_xp[MROWS * G3];   // input projections
__device__ float g_emb[BATCH * DM];

__device__ __forceinline__ float gelu_f(float x) {
    return 0.5f * x * (1.0f + erff(x * 0.70710678118654752f));
}
// HW tanh (MUFU.TANH), ~1e-5 error — far inside the 1e-3 budget.
__device__ __forceinline__ float tanh_hw(float x) {
    float y;
    asm("tanh.approx.f32 %0, %1;" : "=f"(y) : "f"(x));
    return y;
}
__device__ __forceinline__ float sigmoid_hw(float x) {
    return fmaf(0.5f, tanh_hw(0.5f * x), 0.5f);
}

// Blackwell packed fp32 ops on (lo,hi) float pairs.
__device__ __forceinline__ void ffma2(unsigned long long& d,
                                      unsigned long long a,
                                      unsigned long long b) {
    asm("fma.rn.f32x2 %0, %1, %2, %0;" : "+l"(d) : "l"(a), "l"(b));
}
__device__ __forceinline__ unsigned long long fadd2(unsigned long long a,
                                                    unsigned long long b) {
    unsigned long long r;
    asm("add.rn.f32x2 %0, %1, %2;" : "=l"(r) : "l"(a), "l"(b));
    return r;
}
__device__ __forceinline__ unsigned long long fdup2(float v) {
    unsigned long long r;
    asm("mov.b64 %0, {%1, %1};" : "=l"(r) : "r"(__float_as_uint(v)));
    return r;
}
__device__ __forceinline__ unsigned long long pack2(float lo, float hi) {
    unsigned long long r;
    asm("mov.b64 %0, {%1, %2};"
        : "=l"(r) : "r"(__float_as_uint(lo)), "r"(__float_as_uint(hi)));
    return r;
}

__device__ __forceinline__ unsigned smem_u32(const void* p) {
    return (unsigned)__cvta_generic_to_shared(p);
}

// mbarrier wait (parity, acquire) — sleep-based try_wait loop.
__device__ __forceinline__ void mbar_wait_parity(unsigned mb, unsigned par) {
    unsigned done;
    asm volatile(
        "{\n\t.reg .pred p;\n\t"
        "mbarrier.try_wait.parity.acquire.cta.shared::cta.b64 p, [%1], %2;\n\t"
        "selp.b32 %0, 1, 0, p;\n\t}"
        : "=r"(done) : "r"(mb), "r"(par) : "memory");
    if (!done) {
        asm volatile(
            "{\n\t.reg .pred P1;\n\t"
            "WAIT_LOOP_%=:\n\t"
            "mbarrier.try_wait.parity.acquire.cta.shared::cta.b64 P1, [%0], %1, 0x989680;\n\t"
            "@P1 bra.uni WAIT_DONE_%=;\n\t"
            "bra.uni WAIT_LOOP_%=;\n\t"
            "WAIT_DONE_%=:\n\t}"
            :: "r"(mb), "r"(par) : "memory");
    }
}

// ---------------------------------------------------------------------------
// Conv front-end as a GEMM: A = waveform reshaped [32000,160] (contiguous),
// W = conv_w [K=160, N=256] (K-major).  Epilogue: exact GELU + pos_emb.
// ---------------------------------------------------------------------------
__global__ __launch_bounds__(256) void conv_gemm_kernel(
    const float* __restrict__ wave, const float* __restrict__ cw,
    const float* __restrict__ pos)
{
    __shared__ float As[16][64 + 4];
    __shared__ float Ws[16][64 + 4];
    const int bx = blockIdx.x;          // n tile: 0..3
    const int by = blockIdx.y;          // m tile: 0..499
    const int tid = threadIdx.x;

    const float* Ab = wave + by * 64 * PATCH;
    const int lr = tid >> 2;            // 0..63
    const int lc = (tid & 3) << 2;      // 0,4,8,12
    const int wk = tid >> 4;            // 0..15
    const int wn = (tid & 15) << 2;     // 0..60

    const int tr = (tid >> 4) << 2;     // out row base
    const int tc = (tid & 15) << 2;     // out col base

    float acc[4][4] = {};
    for (int bk = 0; bk < PATCH; bk += 16) {
        float4 a = *(const float4*)(Ab + lr * PATCH + bk + lc);
        As[lc + 0][lr] = a.x; As[lc + 1][lr] = a.y;
        As[lc + 2][lr] = a.z; As[lc + 3][lr] = a.w;
        float4 w = *(const float4*)(cw + (bk + wk) * DM + bx * 64 + wn);
        Ws[wk][wn + 0] = w.x; Ws[wk][wn + 1] = w.y;
        Ws[wk][wn + 2] = w.z; Ws[wk][wn + 3] = w.w;
        __syncthreads();
#pragma unroll
        for (int k = 0; k < 16; k++) {
            float am[4], wv[4];
#pragma unroll
            for (int i = 0; i < 4; i++) am[i] = As[k][tr + i];
#pragma unroll
            for (int j = 0; j < 4; j++) wv[j] = Ws[k][tc + j];
#pragma unroll
            for (int i = 0; i < 4; i++)
#pragma unroll
                for (int j = 0; j < 4; j++) acc[i][j] += am[i] * wv[j];
        }
        __syncthreads();
    }
#pragma unroll
    for (int i = 0; i < 4; i++) {
        const int m = by * 64 + tr + i;
        const int s = m % SEQ;
#pragma unroll
        for (int j = 0; j < 4; j++) {
            const int col = bx * 64 + tc + j;
            g_x[m * DM + col] = gelu_f(acc[i][j]) + pos[s * DM + col];
        }
    }
}

// ---------------------------------------------------------------------------
// LayerNorm over last dim (256).  One block per row.  Reads g_x, writes g_xn.
// ---------------------------------------------------------------------------
__global__ __launch_bounds__(256) void ln_kernel(
    const float* __restrict__ sc, const float* __restrict__ bi)
{
    const int m = blockIdx.x;
    const int t = threadIdx.x;
    float v = g_x[m * DM + t];
    float s = v, s2 = v * v;
#pragma unroll
    for (int o = 16; o > 0; o >>= 1) {
        s  += __shfl_xor_sync(0xffffffffu, s,  o);
        s2 += __shfl_xor_sync(0xffffffffu, s2, o);
    }
    __shared__ float ws[8], ws2[8];
    __shared__ float mu_s, rs_s;
    if ((t & 31) == 0) { ws[t >> 5] = s; ws2[t >> 5] = s2; }
    __syncthreads();
    if (t == 0) {
        float a = 0.f, a2 = 0.f;
#pragma unroll
        for (int i = 0; i < 8; i++) { a += ws[i]; a2 += ws2[i]; }
        float mu = a * (1.0f / DM);
        float var = a2 * (1.0f / DM) - mu * mu;
        mu_s = mu;
        rs_s = rsqrtf(var + 1e-5f);
    }
    __syncthreads();
    g_xn[m * DM + t] = (v - mu_s) * rs_s * sc[t] + bi[t];
}

// ---------------------------------------------------------------------------
// Input projection GEMM: g_xp = g_xn @ W^T + b.  W is [768,256] K-major.
// M=32000, N=768, K=256.  CTA tile 128x64, per-thread 8x4 with f32x2 packed
// FFMA (rows packed in pairs; B scalars duplicated into both lanes).
// ---------------------------------------------------------------------------
__global__ __launch_bounds__(256) void proj_gemm_kernel(
    const float* __restrict__ W, const float* __restrict__ bias)
{
    __shared__ float As[16][132];   // [k][m], 128 rows (+pad, keeps 16B align)
    __shared__ float Ws[16][68];    // [k][n], 64 cols
    const int bx = blockIdx.x;      // 0..11 (N tiles)
    const int by = blockIdx.y;      // 0..249 (M tiles)
    const int tid = threadIdx.x;

    const float* Ab = g_xn + (size_t)by * 128 * DM;
    const float* Wb = W + (size_t)bx * 64 * DM;

    const int lr = tid >> 1;            // 0..127 (A row)
    const int lk = (tid & 1) << 3;      // 0 or 8 (A k-offset)
    const int wr = tid >> 2;            // 0..63  (B row)
    const int wk = (tid & 3) << 2;      // 0,4,8,12 (B k-offset)
    const int tr = (tid >> 4) << 3;     // out row base (0..120, step 8)
    const int tc = (tid & 15) << 2;     // out col base (0..60)

    unsigned long long acc[4][4];
#pragma unroll
    for (int i = 0; i < 4; i++)
#pragma unroll
        for (int j = 0; j < 4; j++) acc[i][j] = 0ull;

    for (int bk = 0; bk < DM; bk += 16) {
        float4 a0 = *(const float4*)(Ab + lr * DM + bk + lk);
        float4 a1 = *(const float4*)(Ab + lr * DM + bk + lk + 4);
        As[lk + 0][lr] = a0.x; As[lk + 1][lr] = a0.y;
        As[lk + 2][lr] = a0.z; As[lk + 3][lr] = a0.w;
        As[lk + 4][lr] = a1.x; As[lk + 5][lr] = a1.y;
        As[lk + 6][lr] = a1.z; As[lk + 7][lr] = a1.w;
        float4 w = *(const float4*)(Wb + wr * DM + bk + wk);
        Ws[wk + 0][wr] = w.x; Ws[wk + 1][wr] = w.y;
        Ws[wk + 2][wr] = w.z; Ws[wk + 3][wr] = w.w;
        __syncthreads();
#pragma unroll
        for (int k = 0; k < 16; k++) {
            ulonglong2 av0 = *(const ulonglong2*)&As[k][tr];      // rows tr..tr+3
            ulonglong2 av1 = *(const ulonglong2*)&As[k][tr + 4];  // rows tr+4..tr+7
            float4 wv = *(const float4*)&Ws[k][tc];
            unsigned long long w0 = fdup2(wv.x), w1 = fdup2(wv.y);
            unsigned long long w2 = fdup2(wv.z), w3 = fdup2(wv.w);
            ffma2(acc[0][0], av0.x, w0); ffma2(acc[0][1], av0.x, w1);
            ffma2(acc[0][2], av0.x, w2); ffma2(acc[0][3], av0.x, w3);
            ffma2(acc[1][0], av0.y, w0); ffma2(acc[1][1], av0.y, w1);
            ffma2(acc[1][2], av0.y, w2); ffma2(acc[1][3], av0.y, w3);
            ffma2(acc[2][0], av1.x, w0); ffma2(acc[2][1], av1.x, w1);
            ffma2(acc[2][2], av1.x, w2); ffma2(acc[2][3], av1.x, w3);
            ffma2(acc[3][0], av1.y, w0); ffma2(acc[3][1], av1.y, w1);
            ffma2(acc[3][2], av1.y, w2); ffma2(acc[3][3], av1.y, w3);
        }
        __syncthreads();
    }

    const int gcol = bx * 64 + tc;
    float bj0 = bias[gcol + 0], bj1 = bias[gcol + 1];
    float bj2 = bias[gcol + 2], bj3 = bias[gcol + 3];
#pragma unroll
    for (int i2 = 0; i2 < 4; i2++) {
        const int r0 = by * 128 + tr + 2 * i2;
        float* C0 = g_xp + (size_t)r0 * G3 + gcol;
        float* C1 = C0 + G3;
        union { unsigned long long u; float2 f; } c0, c1, c2, c3;
        c0.u = acc[i2][0]; c1.u = acc[i2][1];
        c2.u = acc[i2][2]; c3.u = acc[i2][3];
        C0[0] = c0.f.x + bj0; C0[1] = c1.f.x + bj1;
        C0[2] = c2.f.x + bj2; C0[3] = c3.f.x + bj3;
        C1[0] = c0.f.y + bj0; C1[1] = c1.f.y + bj1;
        C1[2] = c2.f.y + bj2; C1[3] = c3.f.y + bj3;
    }
}

// ---------------------------------------------------------------------------
// GRU recurrence (R10 structure — best measured).  One 4-CTA cluster per
// batch; each CTA owns a 64-dim slice (192 gate rows).  384 threads:
// (row 0..191, K-half 0..1); 128 f32 weights/thread in registers,
// 4-accumulator f32x2 dot.  Gates: tid<64, one dim each, MUFU tanh.
// h exchange: even gate threads pack (h[2k],h[2k+1]) via shfl and issue
// st.async.b64 into all 4 CTAs' other h buffer (128 stores of 8B vs 256 of
// 4B), tx-counted on each target's parity mbarrier (expect_tx 1024B).
// Wait = try_wait.parity.acquire.  No barrier.cluster in the loop.
// ---------------------------------------------------------------------------
__global__ __launch_bounds__(384, 1) __cluster_dims__(4, 1, 1)
void recur_kernel(const float* __restrict__ Whh,
                  const float* __restrict__ bhh)
{
    __shared__ __align__(16) float h_buf[2][DM];
    __shared__ float gh_sh[192];
    __shared__ __align__(8) unsigned long long mbar[2];

    const int tid   = threadIdx.x;
    const int b     = blockIdx.x >> 2;
    const int slice = blockIdx.x & 3;
    const int d0    = slice * 64;
    const int row   = tid >> 1;         // 0..191
    const int half  = tid & 1;
    const int gate  = row >> 6;         // 0,1,2
    const int dloc  = row & 63;
    const int grow  = gate * DM + d0 + dloc;

    // preload this thread's 128 weights as 64 packed f32x2 pairs
    unsigned long long w2[64];
    {
        const ulonglong2* wp =
            (const ulonglong2*)(Whh + grow * DM + half * 128);
#pragma unroll
        for (int i = 0; i < 32; i++) {
            ulonglong2 v = wp[i];
            w2[2 * i]     = v.x;
            w2[2 * i + 1] = v.y;
        }
    }
    float bhr = 0.f, bhz = 0.f, bhn = 0.f;
    if (tid < 64) {
        bhr = bhh[d0 + tid];
        bhz = bhh[DM + d0 + tid];
        bhn = bhh[2 * DM + d0 + tid];
    }
    if (tid < DM) { h_buf[0][tid] = 0.0f; h_buf[1][tid] = 0.0f; }

    if (tid == 0) {
        asm volatile("mbarrier.init.shared.b64 [%0], %1;"
                     :: "r"(smem_u32(&mbar[0])), "r"(1u) : "memory");
        asm volatile("mbarrier.init.shared.b64 [%0], %1;"
                     :: "r"(smem_u32(&mbar[1])), "r"(1u) : "memory");
    }
    __syncthreads();

    // cluster-wide init barrier: peers' mbarriers + zeroed h visible before
    // any st.async targets them.
    asm volatile("barrier.cluster.arrive.aligned;" ::: "memory");
    asm volatile("barrier.cluster.wait.aligned;"   ::: "memory");

    const float* xpb = g_xp + (size_t)(b * SEQ) * G3;
    int cur = 0;

    // prefetch step 0 inputs (r/z biases folded in)
    float xr = 0.f, xz = 0.f, xnn = 0.f, xold = 0.f;
    if (tid < 64) {
        const float* p = xpb;
        xr   = p[d0 + tid]          + bhr;
        xz   = p[DM + d0 + tid]     + bhz;
        xnn  = p[2 * DM + d0 + tid];
        xold = g_x[(size_t)(b * SEQ) * DM + d0 + tid];
    }

    for (int step = 0; step < SEQ; step++) {
        const unsigned mb_local = smem_u32(&mbar[step & 1]);
        // post this step's expected transaction bytes (4 slices x 256B) and
        // the single arrival.  Early/late relative to incoming tx is fine.
        if (tid == 0) {
            asm volatile("mbarrier.arrive.expect_tx.shared.b64 _, [%0], %1;"
                         :: "r"(mb_local), "r"(1024u) : "memory");
        }

        // partial dot: 64 packed FMAs per thread over 4 independent accs
        unsigned long long a0 = 0ull, a1 = 0ull, a2 = 0ull, a3 = 0ull;
        const ulonglong2* hp = (const ulonglong2*)(&h_buf[cur][half * 128]);
#pragma unroll
        for (int i = 0; i < 16; i++) {
            ulonglong2 hv0 = hp[2 * i];
            ulonglong2 hv1 = hp[2 * i + 1];
            ffma2(a0, w2[4 * i + 0], hv0.x);
            ffma2(a1, w2[4 * i + 1], hv0.y);
            ffma2(a2, w2[4 * i + 2], hv1.x);
            ffma2(a3, w2[4 * i + 3], hv1.y);
        }
        unsigned long long accp = fadd2(fadd2(a0, a1), fadd2(a2, a3));
        union { unsigned long long u; float2 f; } cv; cv.u = accp;
        float sum = cv.f.x + cv.f.y;
        sum += __shfl_down_sync(0xffffffffu, sum, 1);
        if (half == 0) gh_sh[row] = sum;
        __syncthreads();

        if (tid < 64) {
            float r = sigmoid_hw(xr + gh_sh[tid]);
            float z = sigmoid_hw(xz + gh_sh[64 + tid]);
            float n = tanh_hw(xnn + r * (gh_sh[128 + tid] + bhn));
            float hprev = h_buf[cur][d0 + tid];
            float hnew = n + z * (hprev - n);
            g_x[(size_t)(b * SEQ + step) * DM + d0 + tid] = xold + hnew;

            // pair (h[2k], h[2k+1]) within the warp; even tid sends b64 to
            // all 4 CTAs' other buffer, tx-counted on each target's parity
            // mbarrier.  128 stores x 8B per cluster-step = 1024B/target.
            float hnb = __shfl_down_sync(0xffffffffu, hnew, 1);
            if ((tid & 1) == 0) {
                unsigned long long hv2 = pack2(hnew, hnb);
                unsigned laddr = smem_u32(&h_buf[cur ^ 1][d0 + tid]);
#pragma unroll
                for (int peer = 0; peer < 4; peer++) {
                    unsigned raddr, rmb;
                    asm("mapa.shared::cluster.u32 %0, %1, %2;"
                        : "=r"(raddr) : "r"(laddr), "r"(peer));
                    asm("mapa.shared::cluster.u32 %0, %1, %2;"
                        : "=r"(rmb) : "r"(mb_local), "r"(peer));
                    asm volatile(
                        "st.async.shared::cluster.mbarrier::complete_tx::bytes.b64"
                        " [%0], %1, [%2];"
                        :: "r"(raddr), "l"(hv2), "r"(rmb) : "memory");
                }
            }
        }

        // prefetch next step's inputs while stores/peers are in flight
        if (tid < 64 && step + 1 < SEQ) {
            const float* p = xpb + (size_t)(step + 1) * G3;
            xr   = p[d0 + tid]          + bhr;
            xz   = p[DM + d0 + tid]     + bhz;
            xnn  = p[2 * DM + d0 + tid];
            xold = g_x[(size_t)(b * SEQ + step + 1) * DM + d0 + tid];
        }

        // wait for all 1024 bytes (4 slices) + our arrival for this parity
        mbar_wait_parity(mb_local, (unsigned)((step >> 1) & 1));
        cur ^= 1;
    }

    // no CTA may exit while peers might still target its SMEM
    asm volatile("barrier.cluster.arrive.aligned;" ::: "memory");
    asm volatile("barrier.cluster.wait.aligned;"   ::: "memory");
}

// ---------------------------------------------------------------------------
// Mean over sequence: emb[b,d] = mean_t g_xn[b,t,d]
// ---------------------------------------------------------------------------
__global__ __launch_bounds__(256) void mean_kernel()
{
    const int b = blockIdx.x;
    const int t = threadIdx.x;
    float a = 0.f;
#pragma unroll 8
    for (int s = 0; s < SEQ; s++) a += g_xn[(b * SEQ + s) * DM + t];
    g_emb[b * DM + t] = a * (1.0f / SEQ);
}

// ---------------------------------------------------------------------------
// Head: gelu(emb @ w1 + b1) @ w2 + b2.  One block per batch, 128 threads.
// ---------------------------------------------------------------------------
__global__ __launch_bounds__(128) void head_kernel(
    const float* __restrict__ w1, const float* __restrict__ b1,
    const float* __restrict__ w2, const float* __restrict__ b2,
    float* __restrict__ out)
{
    const int b = blockIdx.x;
    const int t = threadIdx.x;
    __shared__ float e_sh[DM];
    __shared__ float h_sh[128];
    e_sh[t]       = g_emb[b * DM + t];
    e_sh[t + 128] = g_emb[b * DM + t + 128];
    __syncthreads();
    float a = b1[t];
#pragma unroll 8
    for (int d = 0; d < DM; d++) a += e_sh[d] * w1[d * 128 + t];
    h_sh[t] = gelu_f(a);
    __syncthreads();
    if (t < 8) {
        float o = b2[t];
#pragma unroll 8
        for (int i = 0; i < 128; i++) o += h_sh[i] * w2[i * 8 + t];
        out[b * 8 + t] = o;
    }
}

// ---------------------------------------------------------------------------
extern "C" void kernel_launch(void* const* d_in, const int* in_sizes, int n_in,
                              void* d_out, int out_size)
{
    const float* waveform    = (const float*)d_in[0];   // [32,160000]
    const float* conv_w      = (const float*)d_in[1];   // [160,256]
    const float* pos_emb     = (const float*)d_in[2];   // [6000,256]
    const float* ln_scale    = (const float*)d_in[3];   // [6,256]
    const float* ln_bias     = (const float*)d_in[4];   // [6,256]
    const float* w_ih        = (const float*)d_in[5];   // [6,768,256]
    const float* w_hh        = (const float*)d_in[6];   // [6,768,256]
    const float* b_ih        = (const float*)d_in[7];   // [6,768]
    const float* b_hh        = (const float*)d_in[8];   // [6,768]
    const float* fnorm_scale = (const float*)d_in[9];   // [256]
    const float* fnorm_bias  = (const float*)d_in[10];  // [256]
    const float* head_w1     = (const float*)d_in[11];  // [256,128]
    const float* head_b1     = (const float*)d_in[12];  // [128]
    const float* head_w2     = (const float*)d_in[13];  // [128,8]
    const float* head_b2     = (const float*)d_in[14];  // [8]
    float* out = (float*)d_out;

    // front-end conv + gelu + pos -> g_x
    conv_gemm_kernel<<<dim3(DM / 64, MROWS / 64), 256>>>(waveform, conv_w, pos_emb);

    for (int l = 0; l < NLAYERS; l++) {
        ln_kernel<<<MROWS, 256>>>(ln_scale + l * DM, ln_bias + l * DM);
        proj_gemm_kernel<<<dim3(G3 / 64, MROWS / 128), 256>>>(
            w_ih + (size_t)l * G3 * DM, b_ih + l * G3);
        recur_kernel<<<BATCH * 4, 384>>>(
            w_hh + (size_t)l * G3 * DM, b_hh + l * G3);
    }

    // final layernorm -> g_xn, mean pool, head
    ln_kernel<<<MROWS, 256>>>(fnorm_scale, fnorm_bias);
    mean_kernel<<<BATCH, 256>>>();
    head_kernel<<<BATCH, 128>>>(head_w1, head_b1, head_w2, head_b2, out);
}

// round 14
// speedup vs baseline: 1.2338x; 1.0755x over previous
#include <cuda_runtime.h>
#include <cuda_bf16.h>

// ---------------------------------------------------------------------------
// MambaAudioClassifier: patchify-conv -> 6x(LN -> GRU -> residual) -> LN ->
// mean pool -> 2-layer head.  B=32, S=1000, D=256, 3D=768, PATCH=160.
// fp32.  Recurrence: R10 structure (best measured): 4-CTA clusters, weights
// in registers, f32x2 FFMA dot, scalar st.async h-exchange + parity
// mbarriers; deltas: MUFU tanh gates, prefetch issued before gate math.
// proj GEMM: f32x2 packed FFMA, 128x64 tile.
// ---------------------------------------------------------------------------

#define BATCH   32
#define SEQ     1000
#define DM      256
#define G3      768
#define PATCH   160
#define NLAYERS 6
#define MROWS   (BATCH * SEQ)       // 32000

// Scratch (device globals: no allocation allowed)
__device__ float g_x [MROWS * DM];   // residual stream
__device__ float g_xn[MROWS * DM];   // layernorm output
__device__ float g_xp[MROWS * G3];   // input projections
__device__ float g_emb[BATCH * DM];

__device__ __forceinline__ float gelu_f(float x) {
    return 0.5f * x * (1.0f + erff(x * 0.70710678118654752f));
}
// HW tanh (MUFU.TANH), ~1e-5 error — far inside the 1e-3 budget.
__device__ __forceinline__ float tanh_hw(float x) {
    float y;
    asm("tanh.approx.f32 %0, %1;" : "=f"(y) : "f"(x));
    return y;
}
__device__ __forceinline__ float sigmoid_hw(float x) {
    return fmaf(0.5f, tanh_hw(0.5f * x), 0.5f);
}

// Blackwell packed fp32 ops on (lo,hi) float pairs.
__device__ __forceinline__ void ffma2(unsigned long long& d,
                                      unsigned long long a,
                                      unsigned long long b) {
    asm("fma.rn.f32x2 %0, %1, %2, %0;" : "+l"(d) : "l"(a), "l"(b));
}
__device__ __forceinline__ unsigned long long fadd2(unsigned long long a,
                                                    unsigned long long b) {
    unsigned long long r;
    asm("add.rn.f32x2 %0, %1, %2;" : "=l"(r) : "l"(a), "l"(b));
    return r;
}
__device__ __forceinline__ unsigned long long fdup2(float v) {
    unsigned long long r;
    asm("mov.b64 %0, {%1, %1};" : "=l"(r) : "r"(__float_as_uint(v)));
    return r;
}

__device__ __forceinline__ unsigned smem_u32(const void* p) {
    return (unsigned)__cvta_generic_to_shared(p);
}

// mbarrier wait (parity, acquire) — sleep-based try_wait loop.
__device__ __forceinline__ void mbar_wait_parity(unsigned mb, unsigned par) {
    unsigned done;
    asm volatile(
        "{\n\t.reg .pred p;\n\t"
        "mbarrier.try_wait.parity.acquire.cta.shared::cta.b64 p, [%1], %2;\n\t"
        "selp.b32 %0, 1, 0, p;\n\t}"
        : "=r"(done) : "r"(mb), "r"(par) : "memory");
    if (!done) {
        asm volatile(
            "{\n\t.reg .pred P1;\n\t"
            "WAIT_LOOP_%=:\n\t"
            "mbarrier.try_wait.parity.acquire.cta.shared::cta.b64 P1, [%0], %1, 0x989680;\n\t"
            "@P1 bra.uni WAIT_DONE_%=;\n\t"
            "bra.uni WAIT_LOOP_%=;\n\t"
            "WAIT_DONE_%=:\n\t}"
            :: "r"(mb), "r"(par) : "memory");
    }
}

// ---------------------------------------------------------------------------
// Conv front-end as a GEMM: A = waveform reshaped [32000,160] (contiguous),
// W = conv_w [K=160, N=256] (K-major).  Epilogue: exact GELU + pos_emb.
// ---------------------------------------------------------------------------
__global__ __launch_bounds__(256) void conv_gemm_kernel(
    const float* __restrict__ wave, const float* __restrict__ cw,
    const float* __restrict__ pos)
{
    __shared__ float As[16][64 + 4];
    __shared__ float Ws[16][64 + 4];
    const int bx = blockIdx.x;          // n tile: 0..3
    const int by = blockIdx.y;          // m tile: 0..499
    const int tid = threadIdx.x;

    const float* Ab = wave + by * 64 * PATCH;
    const int lr = tid >> 2;            // 0..63
    const int lc = (tid & 3) << 2;      // 0,4,8,12
    const int wk = tid >> 4;            // 0..15
    const int wn = (tid & 15) << 2;     // 0..60

    const int tr = (tid >> 4) << 2;     // out row base
    const int tc = (tid & 15) << 2;     // out col base

    float acc[4][4] = {};
    for (int bk = 0; bk < PATCH; bk += 16) {
        float4 a = *(const float4*)(Ab + lr * PATCH + bk + lc);
        As[lc + 0][lr] = a.x; As[lc + 1][lr] = a.y;
        As[lc + 2][lr] = a.z; As[lc + 3][lr] = a.w;
        float4 w = *(const float4*)(cw + (bk + wk) * DM + bx * 64 + wn);
        Ws[wk][wn + 0] = w.x; Ws[wk][wn + 1] = w.y;
        Ws[wk][wn + 2] = w.z; Ws[wk][wn + 3] = w.w;
        __syncthreads();
#pragma unroll
        for (int k = 0; k < 16; k++) {
            float am[4], wv[4];
#pragma unroll
            for (int i = 0; i < 4; i++) am[i] = As[k][tr + i];
#pragma unroll
            for (int j = 0; j < 4; j++) wv[j] = Ws[k][tc + j];
#pragma unroll
            for (int i = 0; i < 4; i++)
#pragma unroll
                for (int j = 0; j < 4; j++) acc[i][j] += am[i] * wv[j];
        }
        __syncthreads();
    }
#pragma unroll
    for (int i = 0; i < 4; i++) {
        const int m = by * 64 + tr + i;
        const int s = m % SEQ;
#pragma unroll
        for (int j = 0; j < 4; j++) {
            const int col = bx * 64 + tc + j;
            g_x[m * DM + col] = gelu_f(acc[i][j]) + pos[s * DM + col];
        }
    }
}

// ---------------------------------------------------------------------------
// LayerNorm over last dim (256).  One block per row.  Reads g_x, writes g_xn.
// ---------------------------------------------------------------------------
__global__ __launch_bounds__(256) void ln_kernel(
    const float* __restrict__ sc, const float* __restrict__ bi)
{
    const int m = blockIdx.x;
    const int t = threadIdx.x;
    float v = g_x[m * DM + t];
    float s = v, s2 = v * v;
#pragma unroll
    for (int o = 16; o > 0; o >>= 1) {
        s  += __shfl_xor_sync(0xffffffffu, s,  o);
        s2 += __shfl_xor_sync(0xffffffffu, s2, o);
    }
    __shared__ float ws[8], ws2[8];
    __shared__ float mu_s, rs_s;
    if ((t & 31) == 0) { ws[t >> 5] = s; ws2[t >> 5] = s2; }
    __syncthreads();
    if (t == 0) {
        float a = 0.f, a2 = 0.f;
#pragma unroll
        for (int i = 0; i < 8; i++) { a += ws[i]; a2 += ws2[i]; }
        float mu = a * (1.0f / DM);
        float var = a2 * (1.0f / DM) - mu * mu;
        mu_s = mu;
        rs_s = rsqrtf(var + 1e-5f);
    }
    __syncthreads();
    g_xn[m * DM + t] = (v - mu_s) * rs_s * sc[t] + bi[t];
}

// ---------------------------------------------------------------------------
// Input projection GEMM: g_xp = g_xn @ W^T + b.  W is [768,256] K-major.
// M=32000, N=768, K=256.  CTA tile 128x64, per-thread 8x4 with f32x2 packed
// FFMA (rows packed in pairs; B scalars duplicated into both lanes).
// ---------------------------------------------------------------------------
__global__ __launch_bounds__(256) void proj_gemm_kernel(
    const float* __restrict__ W, const float* __restrict__ bias)
{
    __shared__ float As[16][132];   // [k][m], 128 rows (+pad, keeps 16B align)
    __shared__ float Ws[16][68];    // [k][n], 64 cols
    const int bx = blockIdx.x;      // 0..11 (N tiles)
    const int by = blockIdx.y;      // 0..249 (M tiles)
    const int tid = threadIdx.x;

    const float* Ab = g_xn + (size_t)by * 128 * DM;
    const float* Wb = W + (size_t)bx * 64 * DM;

    const int lr = tid >> 1;            // 0..127 (A row)
    const int lk = (tid & 1) << 3;      // 0 or 8 (A k-offset)
    const int wr = tid >> 2;            // 0..63  (B row)
    const int wk = (tid & 3) << 2;      // 0,4,8,12 (B k-offset)
    const int tr = (tid >> 4) << 3;     // out row base (0..120, step 8)
    const int tc = (tid & 15) << 2;     // out col base (0..60)

    unsigned long long acc[4][4];
#pragma unroll
    for (int i = 0; i < 4; i++)
#pragma unroll
        for (int j = 0; j < 4; j++) acc[i][j] = 0ull;

    for (int bk = 0; bk < DM; bk += 16) {
        float4 a0 = *(const float4*)(Ab + lr * DM + bk + lk);
        float4 a1 = *(const float4*)(Ab + lr * DM + bk + lk + 4);
        As[lk + 0][lr] = a0.x; As[lk + 1][lr] = a0.y;
        As[lk + 2][lr] = a0.z; As[lk + 3][lr] = a0.w;
        As[lk + 4][lr] = a1.x; As[lk + 5][lr] = a1.y;
        As[lk + 6][lr] = a1.z; As[lk + 7][lr] = a1.w;
        float4 w = *(const float4*)(Wb + wr * DM + bk + wk);
        Ws[wk + 0][wr] = w.x; Ws[wk + 1][wr] = w.y;
        Ws[wk + 2][wr] = w.z; Ws[wk + 3][wr] = w.w;
        __syncthreads();
#pragma unroll
        for (int k = 0; k < 16; k++) {
            ulonglong2 av0 = *(const ulonglong2*)&As[k][tr];      // rows tr..tr+3
            ulonglong2 av1 = *(const ulonglong2*)&As[k][tr + 4];  // rows tr+4..tr+7
            float4 wv = *(const float4*)&Ws[k][tc];
            unsigned long long w0 = fdup2(wv.x), w1 = fdup2(wv.y);
            unsigned long long w2 = fdup2(wv.z), w3 = fdup2(wv.w);
            ffma2(acc[0][0], av0.x, w0); ffma2(acc[0][1], av0.x, w1);
            ffma2(acc[0][2], av0.x, w2); ffma2(acc[0][3], av0.x, w3);
            ffma2(acc[1][0], av0.y, w0); ffma2(acc[1][1], av0.y, w1);
            ffma2(acc[1][2], av0.y, w2); ffma2(acc[1][3], av0.y, w3);
            ffma2(acc[2][0], av1.x, w0); ffma2(acc[2][1], av1.x, w1);
            ffma2(acc[2][2], av1.x, w2); ffma2(acc[2][3], av1.x, w3);
            ffma2(acc[3][0], av1.y, w0); ffma2(acc[3][1], av1.y, w1);
            ffma2(acc[3][2], av1.y, w2); ffma2(acc[3][3], av1.y, w3);
        }
        __syncthreads();
    }

    const int gcol = bx * 64 + tc;
    float bj0 = bias[gcol + 0], bj1 = bias[gcol + 1];
    float bj2 = bias[gcol + 2], bj3 = bias[gcol + 3];
#pragma unroll
    for (int i2 = 0; i2 < 4; i2++) {
        const int r0 = by * 128 + tr + 2 * i2;
        float* C0 = g_xp + (size_t)r0 * G3 + gcol;
        float* C1 = C0 + G3;
        union { unsigned long long u; float2 f; } c0, c1, c2, c3;
        c0.u = acc[i2][0]; c1.u = acc[i2][1];
        c2.u = acc[i2][2]; c3.u = acc[i2][3];
        C0[0] = c0.f.x + bj0; C0[1] = c1.f.x + bj1;
        C0[2] = c2.f.x + bj2; C0[3] = c3.f.x + bj3;
        C1[0] = c0.f.y + bj0; C1[1] = c1.f.y + bj1;
        C1[2] = c2.f.y + bj2; C1[3] = c3.f.y + bj3;
    }
}

// ---------------------------------------------------------------------------
// GRU recurrence (exact R10 structure — best measured — with two deltas:
// MUFU gates, and next-step prefetch issued BEFORE gate math).
// One 4-CTA cluster per batch; each CTA owns a 64-dim slice (192 gate rows).
// 384 threads: (row 0..191, K-half 0..1); 128 f32 weights/thread in
// registers, 4-accumulator f32x2 dot.
// h exchange: each gate thread (tid<64) fires 4 scalar st.async.f32 into all
// 4 CTAs' other h buffer, tx-counted on each target's parity mbarrier
// (expect_tx 1024B).  Wait = try_wait.parity.acquire.
// ---------------------------------------------------------------------------
__global__ __launch_bounds__(384, 1) __cluster_dims__(4, 1, 1)
void recur_kernel(const float* __restrict__ Whh,
                  const float* __restrict__ bhh)
{
    __shared__ __align__(16) float h_buf[2][DM];
    __shared__ float gh_sh[192];
    __shared__ __align__(8) unsigned long long mbar[2];

    const int tid   = threadIdx.x;
    const int b     = blockIdx.x >> 2;
    const int slice = blockIdx.x & 3;
    const int d0    = slice * 64;
    const int row   = tid >> 1;         // 0..191
    const int half  = tid & 1;
    const int gate  = row >> 6;         // 0,1,2
    const int dloc  = row & 63;
    const int grow  = gate * DM + d0 + dloc;

    // preload this thread's 128 weights as 64 packed f32x2 pairs
    unsigned long long w2[64];
    {
        const ulonglong2* wp =
            (const ulonglong2*)(Whh + grow * DM + half * 128);
#pragma unroll
        for (int i = 0; i < 32; i++) {
            ulonglong2 v = wp[i];
            w2[2 * i]     = v.x;
            w2[2 * i + 1] = v.y;
        }
    }
    float bhr = 0.f, bhz = 0.f, bhn = 0.f;
    if (tid < 64) {
        bhr = bhh[d0 + tid];
        bhz = bhh[DM + d0 + tid];
        bhn = bhh[2 * DM + d0 + tid];
    }
    if (tid < DM) { h_buf[0][tid] = 0.0f; h_buf[1][tid] = 0.0f; }

    if (tid == 0) {
        asm volatile("mbarrier.init.shared.b64 [%0], %1;"
                     :: "r"(smem_u32(&mbar[0])), "r"(1u) : "memory");
        asm volatile("mbarrier.init.shared.b64 [%0], %1;"
                     :: "r"(smem_u32(&mbar[1])), "r"(1u) : "memory");
    }
    __syncthreads();

    // cluster-wide init barrier: peers' mbarriers + zeroed h visible before
    // any st.async targets them.
    asm volatile("barrier.cluster.arrive.aligned;" ::: "memory");
    asm volatile("barrier.cluster.wait.aligned;"   ::: "memory");

    const float* xpb = g_xp + (size_t)(b * SEQ) * G3;
    int cur = 0;

    // prefetch step 0 inputs (r/z biases folded in)
    float xr = 0.f, xz = 0.f, xnn = 0.f, xold = 0.f;
    if (tid < 64) {
        const float* p = xpb;
        xr   = p[d0 + tid]          + bhr;
        xz   = p[DM + d0 + tid]     + bhz;
        xnn  = p[2 * DM + d0 + tid];
        xold = g_x[(size_t)(b * SEQ) * DM + d0 + tid];
    }

    for (int step = 0; step < SEQ; step++) {
        const unsigned mb_local = smem_u32(&mbar[step & 1]);
        // post this step's expected transaction bytes (4 slices x 256B) and
        // the single arrival.  Early/late relative to incoming tx is fine.
        if (tid == 0) {
            asm volatile("mbarrier.arrive.expect_tx.shared.b64 _, [%0], %1;"
                         :: "r"(mb_local), "r"(1024u) : "memory");
        }

        // partial dot: 64 packed FMAs per thread over 4 independent accs
        unsigned long long a0 = 0ull, a1 = 0ull, a2 = 0ull, a3 = 0ull;
        const ulonglong2* hp = (const ulonglong2*)(&h_buf[cur][half * 128]);
#pragma unroll
        for (int i = 0; i < 16; i++) {
            ulonglong2 hv0 = hp[2 * i];
            ulonglong2 hv1 = hp[2 * i + 1];
            ffma2(a0, w2[4 * i + 0], hv0.x);
            ffma2(a1, w2[4 * i + 1], hv0.y);
            ffma2(a2, w2[4 * i + 2], hv1.x);
            ffma2(a3, w2[4 * i + 3], hv1.y);
        }
        unsigned long long accp = fadd2(fadd2(a0, a1), fadd2(a2, a3));
        union { unsigned long long u; float2 f; } cv; cv.u = accp;
        float sum = cv.f.x + cv.f.y;
        sum += __shfl_down_sync(0xffffffffu, sum, 1);
        if (half == 0) gh_sh[row] = sum;
        __syncthreads();

        if (tid < 64) {
            // issue next step's loads FIRST (independent of gate math;
            // their DRAM latency then overlaps gates + stores + wait)
            float nxr = 0.f, nxz = 0.f, nxn = 0.f, nxo = 0.f;
            if (step + 1 < SEQ) {
                const float* p = xpb + (size_t)(step + 1) * G3;
                nxr = p[d0 + tid];
                nxz = p[DM + d0 + tid];
                nxn = p[2 * DM + d0 + tid];
                nxo = g_x[(size_t)(b * SEQ + step + 1) * DM + d0 + tid];
            }

            float r = sigmoid_hw(xr + gh_sh[tid]);
            float z = sigmoid_hw(xz + gh_sh[64 + tid]);
            float n = tanh_hw(xnn + r * (gh_sh[128 + tid] + bhn));
            float hprev = h_buf[cur][d0 + tid];
            float hnew = n + z * (hprev - n);
            g_x[(size_t)(b * SEQ + step) * DM + d0 + tid] = xold + hnew;

            // async-store h_new into all 4 CTAs' other buffer, tx-counted on
            // each target's mbarrier for this step parity.
            unsigned laddr = smem_u32(&h_buf[cur ^ 1][d0 + tid]);
#pragma unroll
            for (int peer = 0; peer < 4; peer++) {
                unsigned raddr, rmb;
                asm("mapa.shared::cluster.u32 %0, %1, %2;"
                    : "=r"(raddr) : "r"(laddr), "r"(peer));
                asm("mapa.shared::cluster.u32 %0, %1, %2;"
                    : "=r"(rmb) : "r"(mb_local), "r"(peer));
                asm volatile(
                    "st.async.shared::cluster.mbarrier::complete_tx::bytes.f32"
                    " [%0], %1, [%2];"
                    :: "r"(raddr), "f"(hnew), "r"(rmb) : "memory");
            }

            xr = nxr + bhr;
            xz = nxz + bhz;
            xnn = nxn;
            xold = nxo;
        }

        // wait for all 1024 bytes (4 slices) + our arrival for this parity
        mbar_wait_parity(mb_local, (unsigned)((step >> 1) & 1));
        cur ^= 1;
    }

    // no CTA may exit while peers might still target its SMEM
    asm volatile("barrier.cluster.arrive.aligned;" ::: "memory");
    asm volatile("barrier.cluster.wait.aligned;"   ::: "memory");
}

// ---------------------------------------------------------------------------
// Mean over sequence: emb[b,d] = mean_t g_xn[b,t,d]
// ---------------------------------------------------------------------------
__global__ __launch_bounds__(256) void mean_kernel()
{
    const int b = blockIdx.x;
    const int t = threadIdx.x;
    float a = 0.f;
#pragma unroll 8
    for (int s = 0; s < SEQ; s++) a += g_xn[(b * SEQ + s) * DM + t];
    g_emb[b * DM + t] = a * (1.0f / SEQ);
}

// ---------------------------------------------------------------------------
// Head: gelu(emb @ w1 + b1) @ w2 + b2.  One block per batch, 128 threads.
// ---------------------------------------------------------------------------
__global__ __launch_bounds__(128) void head_kernel(
    const float* __restrict__ w1, const float* __restrict__ b1,
    const float* __restrict__ w2, const float* __restrict__ b2,
    float* __restrict__ out)
{
    const int b = blockIdx.x;
    const int t = threadIdx.x;
    __shared__ float e_sh[DM];
    __shared__ float h_sh[128];
    e_sh[t]       = g_emb[b * DM + t];
    e_sh[t + 128] = g_emb[b * DM + t + 128];
    __syncthreads();
    float a = b1[t];
#pragma unroll 8
    for (int d = 0; d < DM; d++) a += e_sh[d] * w1[d * 128 + t];
    h_sh[t] = gelu_f(a);
    __syncthreads();
    if (t < 8) {
        float o = b2[t];
#pragma unroll 8
        for (int i = 0; i < 128; i++) o += h_sh[i] * w2[i * 8 + t];
        out[b * 8 + t] = o;
    }
}

// ---------------------------------------------------------------------------
extern "C" void kernel_launch(void* const* d_in, const int* in_sizes, int n_in,
                              void* d_out, int out_size)
{
    const float* waveform    = (const float*)d_in[0];   // [32,160000]
    const float* conv_w      = (const float*)d_in[1];   // [160,256]
    const float* pos_emb     = (const float*)d_in[2];   // [6000,256]
    const float* ln_scale    = (const float*)d_in[3];   // [6,256]
    const float* ln_bias     = (const float*)d_in[4];   // [6,256]
    const float* w_ih        = (const float*)d_in[5];   // [6,768,256]
    const float* w_hh        = (const float*)d_in[6];   // [6,768,256]
    const float* b_ih        = (const float*)d_in[7];   // [6,768]
    const float* b_hh        = (const float*)d_in[8];   // [6,768]
    const float* fnorm_scale = (const float*)d_in[9];   // [256]
    const float* fnorm_bias  = (const float*)d_in[10];  // [256]
    const float* head_w1     = (const float*)d_in[11];  // [256,128]
    const float* head_b1     = (const float*)d_in[12];  // [128]
    const float* head_w2     = (const float*)d_in[13];  // [128,8]
    const float* head_b2     = (const float*)d_in[14];  // [8]
    float* out = (float*)d_out;

    // front-end conv + gelu + pos -> g_x
    conv_gemm_kernel<<<dim3(DM / 64, MROWS / 64), 256>>>(waveform, conv_w, pos_emb);

    for (int l = 0; l < NLAYERS; l++) {
        ln_kernel<<<MROWS, 256>>>(ln_scale + l * DM, ln_bias + l * DM);
        proj_gemm_kernel<<<dim3(G3 / 64, MROWS / 128), 256>>>(
            w_ih + (size_t)l * G3 * DM, b_ih + l * G3);
        recur_kernel<<<BATCH * 4, 384>>>(
            w_hh + (size_t)l * G3 * DM, b_hh + l * G3);
    }

    // final layernorm -> g_xn, mean pool, head
    ln_kernel<<<MROWS, 256>>>(fnorm_scale, fnorm_bias);
    mean_kernel<<<BATCH, 256>>>();
    head_kernel<<<BATCH, 128>>>(head_w1, head_b1, head_w2, head_b2, out);
}